// round 13
// baseline (speedup 1.0000x reference)
#include <cuda_runtime.h>
#include <cuda_fp16.h>

#define NUSERS  100000
#define NNODES  300000
#define NEDGES  1250000
#define HID     64
#define EIG     16
#define NPATHS  14
#define LN_EPS  1e-5f

#define SCAN_BLK 1024
#define NBLK1    ((NNODES + SCAN_BLK - 1) / SCAN_BLK)   // 293
#define NG4      (NEDGES / 4)                            // 312500 edge quads

// ---------------- scratch (device globals: no allocation allowed) ----------
__device__ float  g_yA[(size_t)NNODES * HID];    // f32 layernormed emb (L0)
__device__ float  g_yB[(size_t)NNODES * HID];    // f32 layernormed emb (L1)
__device__ __half g_hA[(size_t)NNODES * HID];    // fp16 copy for score (L0)
__device__ __half g_hB[(size_t)NNODES * HID];    // fp16 copy for score (L1)
__device__ __align__(16) int2  g_edge[NEDGES];   // {row, col|pt<<19} sorted by row
__device__ __align__(16) float g_yeig[NEDGES];   // dot(eig[r],eig[c]) per edge
__device__ __align__(16) float g_e0[NEDGES];     // exp(s0) per sorted edge
__device__ int    g_count[NNODES];               // row degree
__device__ int    g_off[NNODES];                 // CSR row offsets
__device__ int    g_cursor[NNODES];              // scatter cursors
__device__ int    g_total;                       // scan base allocator

// ---------------------------------------------------------------------------
__device__ __forceinline__ void store_h4(__half* hbase, int row, int lane, float4 v) {
    union { uint2 u; __half2 h[2]; } pk;
    pk.h[0] = __floats2half2_rn(v.x, v.y);
    pk.h[1] = __floats2half2_rn(v.z, v.w);
    ((uint2*)(hbase + (size_t)row * HID))[lane] = pk.u;
}

__device__ __forceinline__ float hdot8(uint2 ur, uint2 uc) {
    float2 a = __half22float2(*(const __half2*)&ur.x);
    float2 b = __half22float2(*(const __half2*)&uc.x);
    float p = a.x * b.x + a.y * b.y;
    a = __half22float2(*(const __half2*)&ur.y);
    b = __half22float2(*(const __half2*)&uc.y);
    return p + a.x * b.x + a.y * b.y;
}

// ---------------------------------------------------------------------------
__global__ void k_zero() {
    int i = blockIdx.x * blockDim.x + threadIdx.x;
    if (i < NNODES) g_count[i] = 0;
    if (i == 0) g_total = 0;
}

// ---------------------------------------------------------------------------
// Layer-0 layernorm (half-warp per row, float4 lanes) + folded edge COUNT:
// threads tid < NEDGES also histogram idx rows (atomics hide under the
// kernel's streaming traffic).  g_yA/g_hA = LN(concat); out = concat (emb0).
__global__ void __launch_bounds__(256) k_ln0(const float* __restrict__ ue,
                                             const float* __restrict__ ie,
                                             const int* __restrict__ idx,
                                             float* __restrict__ out) {
    int tid  = blockIdx.x * blockDim.x + threadIdx.x;
    int row  = tid >> 4;
    int lane = threadIdx.x & 15;
    if (row >= NNODES) return;

    if (tid < NEDGES) atomicAdd(&g_count[idx[tid]], 1);   // folded k_count

    const float* src = (row < NUSERS)
        ? ue + (size_t)row * HID
        : ie + (size_t)(row - NUSERS) * HID;
    float4 v = ((const float4*)src)[lane];

    float s  = v.x + v.y + v.z + v.w;
    float sq = v.x * v.x + v.y * v.y + v.z * v.z + v.w * v.w;
    #pragma unroll
    for (int o = 8; o; o >>= 1) {
        s  += __shfl_xor_sync(0xFFFFFFFFu, s,  o);
        sq += __shfl_xor_sync(0xFFFFFFFFu, sq, o);
    }
    float mu  = s * (1.0f / HID);
    float var = sq * (1.0f / HID) - mu * mu;
    float r   = rsqrtf(var + LN_EPS);

    float4 o4;
    o4.x = (v.x - mu) * r;
    o4.y = (v.y - mu) * r;
    o4.z = (v.z - mu) * r;
    o4.w = (v.w - mu) * r;
    ((float4*)(g_yA + (size_t)row * HID))[lane] = o4;
    store_h4(g_hA, row, lane, o4);
    ((float4*)(out + (size_t)row * HID))[lane] = v;
}

// ------------------------------ CSR build ----------------------------------
__device__ __forceinline__ int block_incl_scan(int v, int* ws) {
    int lane = threadIdx.x & 31, wid = threadIdx.x >> 5;
    int x = v;
    #pragma unroll
    for (int o = 1; o < 32; o <<= 1) {
        int t = __shfl_up_sync(0xFFFFFFFFu, x, o);
        if (lane >= o) x += t;
    }
    if (lane == 31) ws[wid] = x;
    __syncthreads();
    if (wid == 0) {
        int y = (lane < (blockDim.x >> 5)) ? ws[lane] : 0;
        #pragma unroll
        for (int o = 1; o < 32; o <<= 1) {
            int t = __shfl_up_sync(0xFFFFFFFFu, y, o);
            if (lane >= o) y += t;
        }
        ws[lane] = y;
    }
    __syncthreads();
    return x + (wid ? ws[wid - 1] : 0);
}

// Block-local scan + atomic base grab (CSR needs only disjoint slices).
__global__ void k_scan() {
    __shared__ int ws[32];
    __shared__ int s_base;
    int gid = blockIdx.x * SCAN_BLK + threadIdx.x;
    int v = (gid < NNODES) ? g_count[gid] : 0;
    int incl = block_incl_scan(v, ws);
    if (threadIdx.x == SCAN_BLK - 1) s_base = atomicAdd(&g_total, incl);
    __syncthreads();
    if (gid < NNODES) {
        int o = s_base + incl - v;
        g_off[gid]    = o;
        g_cursor[gid] = o;
    }
}

__global__ void k_scatter(const int* __restrict__ idx,
                          const int* __restrict__ ptype) {
    int e = blockIdx.x * blockDim.x + threadIdx.x;
    if (e >= NEDGES) return;
    int row = idx[e];
    int pos = atomicAdd(&g_cursor[row], 1);
    g_edge[pos] = make_int2(row, idx[NEDGES + e] | (ptype[e] << 19));
}

// ---------------------------------------------------------------------------
// Pre-pass: layer-independent eig dots, 4 edges per half-warp (4 chains).
__global__ void __launch_bounds__(256) k_prep(const float* __restrict__ eigs) {
    int tid  = blockIdx.x * blockDim.x + threadIdx.x;
    int g    = tid >> 4;
    int lane = threadIdx.x & 15;
    if (g >= NG4) return;

    int4 eA = ((const int4*)g_edge)[2 * g];       // edges 4g, 4g+1
    int4 eB = ((const int4*)g_edge)[2 * g + 1];   // edges 4g+2, 4g+3

    float p0 = eigs[(size_t)eA.x * EIG + lane] * eigs[(size_t)(eA.y & 0x7FFFF) * EIG + lane];
    float p1 = eigs[(size_t)eA.z * EIG + lane] * eigs[(size_t)(eA.w & 0x7FFFF) * EIG + lane];
    float p2 = eigs[(size_t)eB.x * EIG + lane] * eigs[(size_t)(eB.y & 0x7FFFF) * EIG + lane];
    float p3 = eigs[(size_t)eB.z * EIG + lane] * eigs[(size_t)(eB.w & 0x7FFFF) * EIG + lane];
    #pragma unroll
    for (int o = 8; o; o >>= 1) {
        p0 += __shfl_xor_sync(0xFFFFFFFFu, p0, o);
        p1 += __shfl_xor_sync(0xFFFFFFFFu, p1, o);
        p2 += __shfl_xor_sync(0xFFFFFFFFu, p2, o);
        p3 += __shfl_xor_sync(0xFFFFFFFFu, p3, o);
    }
    if (lane == 0) ((float4*)g_yeig)[g] = make_float4(p0, p1, p2, p3);
}

// ---------------------------------------------------------------------------
// Edge-parallel score, 4 edges per half-warp (4 interleaved chains), fp16 y.
//   g_e0[pos] = exp(dot(y[r],y[c])/8 + exp(lam)*g_yeig[pos])
// (Softmax max-shift dropped: ratio shift-invariant, magnitudes f32-safe.)
__global__ void __launch_bounds__(256) k_score(const __half* __restrict__ hy,
                                               const float* __restrict__ lam_l) {
    int tid  = blockIdx.x * blockDim.x + threadIdx.x;
    int g    = tid >> 4;
    int lane = threadIdx.x & 15;
    if (g >= NG4) return;

    int4 eA = ((const int4*)g_edge)[2 * g];
    int4 eB = ((const int4*)g_edge)[2 * g + 1];

    uint2 r0 = ((const uint2*)(hy + (size_t)eA.x * HID))[lane];
    uint2 c0 = ((const uint2*)(hy + (size_t)(eA.y & 0x7FFFF) * HID))[lane];
    uint2 r1 = ((const uint2*)(hy + (size_t)eA.z * HID))[lane];
    uint2 c1 = ((const uint2*)(hy + (size_t)(eA.w & 0x7FFFF) * HID))[lane];
    uint2 r2 = ((const uint2*)(hy + (size_t)eB.x * HID))[lane];
    uint2 c2 = ((const uint2*)(hy + (size_t)(eB.y & 0x7FFFF) * HID))[lane];
    uint2 r3 = ((const uint2*)(hy + (size_t)eB.z * HID))[lane];
    uint2 c3 = ((const uint2*)(hy + (size_t)(eB.w & 0x7FFFF) * HID))[lane];

    float p0 = hdot8(r0, c0);
    float p1 = hdot8(r1, c1);
    float p2 = hdot8(r2, c2);
    float p3 = hdot8(r3, c3);

    #pragma unroll
    for (int o = 8; o; o >>= 1) {
        p0 += __shfl_xor_sync(0xFFFFFFFFu, p0, o);
        p1 += __shfl_xor_sync(0xFFFFFFFFu, p1, o);
        p2 += __shfl_xor_sync(0xFFFFFFFFu, p2, o);
        p3 += __shfl_xor_sync(0xFFFFFFFFu, p3, o);
    }

    if (lane == 0) {
        float elam = __expf(lam_l[0]);
        float4 ye = ((const float4*)g_yeig)[g];
        float4 e;
        e.x = __expf(p0 * 0.125f + elam * ye.x);
        e.y = __expf(p1 * 0.125f + elam * ye.y);
        e.z = __expf(p2 * 0.125f + elam * ye.z);
        e.w = __expf(p3 * 0.125f + elam * ye.w);
        ((float4*)g_e0)[g] = e;
    }
}

// ---------------------------------------------------------------------------
// Row-parallel aggregation, half-warp per row, TWO interleaved edge chains.
// Linearity: res = 0.5*(Σe0·y[c])/Σe0 + 0.5*(Σep·y[c])/Σep.
//   final==0 : out += res ; ydst/hdst = LN(res)
//   final==1 : out = (out + res) / 3
__global__ void __launch_bounds__(256) k_agg(const float* __restrict__ ysrc,
                                             float* __restrict__ ydst,
                                             __half* __restrict__ hdst,
                                             const float* __restrict__ pemb,
                                             float* __restrict__ out,
                                             int final_mode) {
    __shared__ float s_ep[NPATHS];
    if (threadIdx.x < NPATHS) s_ep[threadIdx.x] = __expf(pemb[threadIdx.x]);
    __syncthreads();

    int tid  = blockIdx.x * blockDim.x + threadIdx.x;
    int row  = tid >> 4;
    int lane = threadIdx.x & 15;
    if (row >= NNODES) return;

    int start = g_off[row];
    int end   = start + g_count[row];

    float4 a0A = make_float4(0.f,0.f,0.f,0.f), a1A = make_float4(0.f,0.f,0.f,0.f);
    float4 a0B = make_float4(0.f,0.f,0.f,0.f), a1B = make_float4(0.f,0.f,0.f,0.f);
    float  d0A = 0.f, d1A = 0.f, d0B = 0.f, d1B = 0.f;

    int pos = start;
    for (; pos + 2 <= end; pos += 2) {
        int   pkA = g_edge[pos].y;
        int   pkB = g_edge[pos + 1].y;
        float e0A = g_e0[pos];
        float e0B = g_e0[pos + 1];
        float epA = s_ep[pkA >> 19];
        float epB = s_ep[pkB >> 19];
        float4 ycA = ((const float4*)(ysrc + (size_t)(pkA & 0x7FFFF) * HID))[lane];
        float4 ycB = ((const float4*)(ysrc + (size_t)(pkB & 0x7FFFF) * HID))[lane];
        d0A += e0A;  d1A += epA;
        d0B += e0B;  d1B += epB;
        a0A.x += e0A * ycA.x;  a0A.y += e0A * ycA.y;
        a0A.z += e0A * ycA.z;  a0A.w += e0A * ycA.w;
        a1A.x += epA * ycA.x;  a1A.y += epA * ycA.y;
        a1A.z += epA * ycA.z;  a1A.w += epA * ycA.w;
        a0B.x += e0B * ycB.x;  a0B.y += e0B * ycB.y;
        a0B.z += e0B * ycB.z;  a0B.w += e0B * ycB.w;
        a1B.x += epB * ycB.x;  a1B.y += epB * ycB.y;
        a1B.z += epB * ycB.z;  a1B.w += epB * ycB.w;
    }
    if (pos < end) {
        int   pk = g_edge[pos].y;
        float e0 = g_e0[pos];
        float ep = s_ep[pk >> 19];
        float4 yc = ((const float4*)(ysrc + (size_t)(pk & 0x7FFFF) * HID))[lane];
        d0A += e0;  d1A += ep;
        a0A.x += e0 * yc.x;  a0A.y += e0 * yc.y;
        a0A.z += e0 * yc.z;  a0A.w += e0 * yc.w;
        a1A.x += ep * yc.x;  a1A.y += ep * yc.y;
        a1A.z += ep * yc.z;  a1A.w += ep * yc.w;
    }

    float den0 = d0A + d0B, den1 = d1A + d1B;
    float4 res = make_float4(0.f, 0.f, 0.f, 0.f);
    if (end > start) {
        float i0 = 0.5f / den0;
        float i1 = 0.5f / den1;
        res.x = (a0A.x + a0B.x) * i0 + (a1A.x + a1B.x) * i1;
        res.y = (a0A.y + a0B.y) * i0 + (a1A.y + a1B.y) * i1;
        res.z = (a0A.z + a0B.z) * i0 + (a1A.z + a1B.z) * i1;
        res.w = (a0A.w + a0B.w) * i0 + (a1A.w + a1B.w) * i1;
    }

    float4* op = (float4*)(out + (size_t)row * HID);
    if (final_mode) {
        float4 cur = op[lane];
        cur.x = (cur.x + res.x) * (1.0f / 3.0f);
        cur.y = (cur.y + res.y) * (1.0f / 3.0f);
        cur.z = (cur.z + res.z) * (1.0f / 3.0f);
        cur.w = (cur.w + res.w) * (1.0f / 3.0f);
        op[lane] = cur;
    } else {
        float4 cur = op[lane];
        cur.x += res.x; cur.y += res.y; cur.z += res.z; cur.w += res.w;
        op[lane] = cur;

        // LN(res) -> ydst/hdst for next layer (epilogue only)
        float s  = res.x + res.y + res.z + res.w;
        float sq = res.x * res.x + res.y * res.y + res.z * res.z + res.w * res.w;
        #pragma unroll
        for (int o = 8; o; o >>= 1) {
            s  += __shfl_xor_sync(0xFFFFFFFFu, s,  o);
            sq += __shfl_xor_sync(0xFFFFFFFFu, sq, o);
        }
        float mu  = s * (1.0f / HID);
        float var = sq * (1.0f / HID) - mu * mu;
        float rr  = rsqrtf(var + LN_EPS);
        float4 o4;
        o4.x = (res.x - mu) * rr;
        o4.y = (res.y - mu) * rr;
        o4.z = (res.z - mu) * rr;
        o4.w = (res.w - mu) * rr;
        ((float4*)(ydst + (size_t)row * HID))[lane] = o4;
        store_h4(hdst, row, lane, o4);
    }
}

// ---------------------------------------------------------------------------
extern "C" void kernel_launch(void* const* d_in, const int* in_sizes, int n_in,
                              void* d_out, int out_size) {
    const float* ue   = (const float*)d_in[0];
    const float* ie   = (const float*)d_in[1];
    const float* eigs = (const float*)d_in[2];
    const float* lam  = (const float*)d_in[3];
    const float* pw   = (const float*)d_in[4];
    const int*   idx  = (const int*)d_in[5];
    const int*   pt   = (const int*)d_in[6];
    float*       out  = (float*)d_out;

    float *yA, *yB;
    __half *hA, *hB;
    cudaGetSymbolAddress((void**)&yA, g_yA);
    cudaGetSymbolAddress((void**)&yB, g_yB);
    cudaGetSymbolAddress((void**)&hA, g_hA);
    cudaGetSymbolAddress((void**)&hB, g_hB);

    const int node_grid = (NNODES + 255) / 256;
    const int edge_grid = (NEDGES + 255) / 256;
    const int half_grid = ((NNODES * 16) + 255) / 256;   // half-warp per row
    const int quad_grid = ((NG4 * 16) + 255) / 256;      // half-warp per 4 edges

    // zero -> ln0(+count) -> scan -> scatter -> prep
    k_zero   <<<node_grid, 256>>>();
    k_ln0    <<<half_grid, 256>>>(ue, ie, idx, out);
    k_scan   <<<NBLK1, SCAN_BLK>>>();
    k_scatter<<<edge_grid, 256>>>(idx, pt);
    k_prep   <<<quad_grid, 256>>>(eigs);

    // layer 0: score(fp16 yA) -> agg(f32 yA) ; out += emb1, yB/hB = LN(emb1)
    k_score<<<quad_grid, 256>>>(hA, lam + 0);
    k_agg  <<<half_grid, 256>>>(yA, yB, hB, pw + 0 * NPATHS, out, 0);

    // layer 1: score(fp16 yB) -> agg(f32 yB) -> out = (out + emb2)/3
    k_score<<<quad_grid, 256>>>(hB, lam + 1);
    k_agg  <<<half_grid, 256>>>(yB, yA, hA, pw + 1 * NPATHS, out, 1);
}